// round 14
// baseline (speedup 1.0000x reference)
#include <cuda_runtime.h>
#include <cuda_bf16.h>

// Problem constants
#define B 4
#define N 256
#define F 128
#define H 256

typedef unsigned long long ull;

// Scratch (allocation-free rule: __device__ globals)
__device__ __align__(16) float g_ub[B * H];     // u[b,h] + b1[h]
__device__ __align__(16) float g_A[B * N * H];  // relu(x_i) @ W1_i   (raw, no ub)
__device__ __align__(16) float g_C[B * N * H];  // relu(x_j) @ W1_j

// ---- packed f32x2 helpers (sm_100+) ---------------------------------------
static __device__ __forceinline__ ull add2(ull a, ull b) {
    ull d; asm("add.rn.f32x2 %0, %1, %2;" : "=l"(d) : "l"(a), "l"(b)); return d;
}
static __device__ __forceinline__ ull fma2(ull a, ull b, ull c) {
    ull d; asm("fma.rn.f32x2 %0, %1, %2, %3;" : "=l"(d) : "l"(a), "l"(b), "l"(c)); return d;
}
static __device__ __forceinline__ ull pack2(float lo, float hi) {
    ull d; asm("mov.b64 %0, {%1, %2};" : "=l"(d) : "f"(lo), "f"(hi)); return d;
}
static __device__ __forceinline__ void unpack2(ull v, float& lo, float& hi) {
    asm("mov.b64 {%0, %1}, %2;" : "=f"(lo), "=f"(hi) : "l"(v));
}
static __device__ __forceinline__ ull relu2(ull v) {
    float lo, hi; unpack2(v, lo, hi);
    return pack2(fmaxf(lo, 0.f), fmaxf(hi, 0.f));
}
static __device__ __forceinline__ float hsum2(ull v) {
    float lo, hi; unpack2(v, lo, hi); return lo + hi;
}

// ---------------------------------------------------------------------------
// Kernel 1: fused nodegemm (blocks 0..255) + pool (blocks 256..259).
//   256 threads.  Gemm blocks: (row-group of 8 rows) x (h-half of 128).
//   256 gemm blocks -> 1.73 blocks/SM: cross-block latency hiding.
// ---------------------------------------------------------------------------
#define CF 16         // f per chunk
#define NCHUNK (F / CF)
#define HW 128        // h per gemm block
#define GROWS 8       // rows per gemm block

__global__ void __launch_bounds__(256) k_main(
        const float* __restrict__ x,
        const float* __restrict__ Wp,
        const float* __restrict__ W1,
        const float* __restrict__ b1) {
    __shared__ __align__(16) float rx[F * GROWS];          // [f][8 rows] 4 KB
    __shared__ __align__(16) float wbuf[2][CF][2][HW];     // 32 KB staged W1a/W1c
    int tid = threadIdx.x;

    if (blockIdx.x < 256) {
        // ================== nodegemm ==================
        int row0 = (blockIdx.x >> 1) * GROWS;  // 8 rows per block
        int h0   = (blockIdx.x & 1) * HW;      // h-half
        int hl = tid & (HW - 1);               // 0..127
        int rg = tid >> 7;                     // 0..1 -> rows rg*4..rg*4+3

        // rx packed: word f*8 + r  => row-pairs contiguous (8B)
        #pragma unroll
        for (int k = 0; k < 4; k++) {
            int idx = tid + k * 256;
            int r = idx >> 7, f = idx & (F - 1);
            rx[f * GROWS + r] = fmaxf(x[(row0 + r) * F + f], 0.f);
        }

        const float* W1base = W1 + (size_t)F * H + h0;  // rows [F,3F), this h-half

        // prologue: fetch chunk 0 and stage it
        float4 t0, t1, t2, t3;
        {
            #pragma unroll
            for (int k = 0; k < 4; k++) {
                int idx = tid + k * 256;            // 0..1023 float4s
                int part = idx >> 9;                // 0 = A-weights, 1 = C
                int rem = idx & 511;
                int fl = rem >> 5, q = rem & 31;
                float4 v = ((const float4*)(W1base + ((size_t)(part * F + fl)) * H))[q];
                if (k == 0) t0 = v; else if (k == 1) t1 = v;
                else if (k == 2) t2 = v; else t3 = v;
            }
            #pragma unroll
            for (int k = 0; k < 4; k++) {
                int idx = tid + k * 256;
                int part = idx >> 9;
                int rem = idx & 511;
                int fl = rem >> 5, q = rem & 31;
                float4 v = (k == 0) ? t0 : (k == 1) ? t1 : (k == 2) ? t2 : t3;
                ((float4*)&wbuf[0][fl][part][0])[q] = v;
            }
        }
        __syncthreads();

        const longlong2* rxq = (const longlong2*)rx;  // [F][2] 16B row-quads
        ull accA[2] = {0, 0};
        ull accC[2] = {0, 0};

        for (int c = 0; c < NCHUNK; c++) {
            int s = c & 1;
            bool pf = (c + 1) < NCHUNK;
            // prefetch next chunk into registers
            if (pf) {
                int fb = (c + 1) * CF;
                #pragma unroll
                for (int k = 0; k < 4; k++) {
                    int idx = tid + k * 256;
                    int part = idx >> 9;
                    int rem = idx & 511;
                    int fl = rem >> 5, q = rem & 31;
                    float4 v = ((const float4*)(W1base + ((size_t)(part * F + fb + fl)) * H))[q];
                    if (k == 0) t0 = v; else if (k == 1) t1 = v;
                    else if (k == 2) t2 = v; else t3 = v;
                }
            }
            // compute current chunk from smem
            #pragma unroll
            for (int fl = 0; fl < CF; fl++) {
                int f = c * CF + fl;
                float wa = wbuf[s][fl][0][hl];
                float wc = wbuf[s][fl][1][hl];
                ull wa2 = pack2(wa, wa);
                ull wc2 = pack2(wc, wc);
                longlong2 p01 = rxq[f * 2 + rg];     // LDS.128 broadcast (rows 4rg..4rg+3)
                ull v0 = (ull)p01.x, v1 = (ull)p01.y;
                accA[0] = fma2(v0, wa2, accA[0]);
                accA[1] = fma2(v1, wa2, accA[1]);
                accC[0] = fma2(v0, wc2, accC[0]);
                accC[1] = fma2(v1, wc2, accC[1]);
            }
            // stage prefetched chunk
            if (pf) {
                int ns = (c + 1) & 1;
                #pragma unroll
                for (int k = 0; k < 4; k++) {
                    int idx = tid + k * 256;
                    int part = idx >> 9;
                    int rem = idx & 511;
                    int fl = rem >> 5, q = rem & 31;
                    float4 v = (k == 0) ? t0 : (k == 1) ? t1 : (k == 2) ? t2 : t3;
                    ((float4*)&wbuf[ns][fl][part][0])[q] = v;
                }
            }
            __syncthreads();
        }

        #pragma unroll
        for (int p = 0; p < 2; p++) {
            int r0g = row0 + rg * 4 + 2 * p;
            float a0, a1, c0, c1;
            unpack2(accA[p], a0, a1);
            unpack2(accC[p], c0, c1);
            g_A[r0g * H + h0 + hl]       = a0;
            g_A[(r0g + 1) * H + h0 + hl] = a1;
            g_C[r0g * H + h0 + hl]       = c0;
            g_C[(r0g + 1) * H + h0 + hl] = c1;
        }
    } else {
        // ================== pool ==================
        int b = blockIdx.x - 256;
        float* part2 = rx;              // [2][F]
        float* m     = rx + 256;        // [F]
        float* r     = rx + 384;        // [F]
        const float* xb = x + b * N * F;

        // Phase 1: column mean (2 groups x 128 nodes, 4 indep accumulators)
        {
            int f = tid & (F - 1);
            int g = tid >> 7;
            const float* base = xb + g * 128 * F + f;
            float s0 = 0.f, s1 = 0.f, s2 = 0.f, s3 = 0.f;
            #pragma unroll
            for (int n = 0; n < 32; n++) {
                s0 += base[(n) * F];
                s1 += base[(n + 32) * F];
                s2 += base[(n + 64) * F];
                s3 += base[(n + 96) * F];
            }
            part2[g * F + f] = (s0 + s1) + (s2 + s3);
        }
        __syncthreads();
        if (tid < F) m[tid] = (part2[tid] + part2[F + tid]) * (1.0f / N);
        __syncthreads();

        // Phase 2: hp[f] = relu(sum m[fin] * Wp[fin, f])
        {
            int f = tid & (F - 1);
            int g = tid >> 7;
            float s0 = 0.f, s1 = 0.f;
            #pragma unroll
            for (int k = 0; k < 32; k++) {
                int fin = g * 64 + k;
                s0 += m[fin] * Wp[fin * F + f];
                s1 += m[fin + 32] * Wp[(fin + 32) * F + f];
            }
            part2[g * F + f] = s0 + s1;
        }
        __syncthreads();
        if (tid < F) r[tid] = fmaxf(part2[tid] + part2[F + tid], 0.f);
        __syncthreads();

        // Phase 3: u[h] = sum_f r[f] * W1[f, h] + b1[h]
        {
            int h = tid;
            float s0 = 0.f, s1 = 0.f, s2 = 0.f, s3 = 0.f;
            #pragma unroll
            for (int f = 0; f < 32; f++) {
                s0 += r[f]      * W1[f * H + h];
                s1 += r[f + 32] * W1[(f + 32) * H + h];
                s2 += r[f + 64] * W1[(f + 64) * H + h];
                s3 += r[f + 96] * W1[(f + 96) * H + h];
            }
            g_ub[b * H + h] = (s0 + s1) + (s2 + s3) + b1[h];
        }
    }
}

// ---------------------------------------------------------------------------
// Kernel 2: pairwise fused readout (R5 verbatim).  grid(8,8,B), block(256)
//   32x32 tile; thread (tj, ti, hh): 4i x 2j partials over its 64-h slice of
//   each 128-h half; 2-way smem reduction combines hh slices.
// ---------------------------------------------------------------------------
#define HS 128          // h per smem-resident half
#define RQ 130          // row stride in floats (130%32==2: conflict-free LDS.64)
#define RQU 65          // row stride in ull

__global__ void __launch_bounds__(256) k_pair(
        const float* __restrict__ W2,
        const float* __restrict__ b2,
        float* __restrict__ out) {
    __shared__ __align__(16) float As[32 * RQ];
    __shared__ __align__(16) float Cs[32 * RQ];
    __shared__ __align__(16) float w2s[H];
    __shared__ __align__(16) float ubs[H];
    __shared__ __align__(16) float psum[128][9];

    int b  = blockIdx.z;
    int i0 = blockIdx.y * 32;
    int j0 = blockIdx.x * 32;
    int tid = threadIdx.x;

    if (tid < 128) {
        w2s[tid] = W2[tid];
        w2s[tid + 128] = W2[tid + 128];
        ubs[tid] = g_ub[b * H + tid];
        ubs[tid + 128] = g_ub[b * H + tid + 128];
    }

    int tj = tid & 15;          // j-group: cols tj, tj+16
    int ti = (tid >> 4) & 7;    // i-group: rows ti, ti+8, ti+16, ti+24
    int hh = tid >> 7;          // h-slice within each half (0 or 1)

    ull acc00 = 0, acc01 = 0;   // row ti
    ull acc10 = 0, acc11 = 0;   // row ti+8
    ull acc20 = 0, acc21 = 0;   // row ti+16
    ull acc30 = 0, acc31 = 0;   // row ti+24

    #pragma unroll
    for (int half = 0; half < 2; half++) {
        int ho = half * HS;
        __syncthreads();        // (also covers w2s/ubs readiness on half 0)
        // ---- fill tiles (ub folded into A); 256 threads, 4+4 float4 each ----
        #pragma unroll
        for (int k = 0; k < 4; k++) {
            int idx = tid + k * 256;        // 0..1023: r = idx>>5, q = idx&31
            int r = idx >> 5, q = idx & 31;
            float4 a = ((const float4*)(g_A + ((size_t)(b * N + i0 + r)) * H + ho))[q];
            float4 u = ((const float4*)(ubs + ho))[q];
            float2* da = (float2*)(As + r * RQ + 4 * q);
            da[0] = make_float2(a.x + u.x, a.y + u.y);
            da[1] = make_float2(a.z + u.z, a.w + u.w);
            float4 c = ((const float4*)(g_C + ((size_t)(b * N + j0 + r)) * H + ho))[q];
            float2* dc = (float2*)(Cs + r * RQ + 4 * q);
            dc[0] = make_float2(c.x, c.y);
            dc[1] = make_float2(c.z, c.w);
        }
        __syncthreads();

        // ---- compute: this thread's 32 h-pairs of this half ----
        int hq = hh * 32;                    // ull offset within row
        const ull* a0p = (const ull*)As + (size_t)ti * RQU + hq;
        const ull* a1p = a0p + 8 * RQU;
        const ull* a2p = a0p + 16 * RQU;
        const ull* a3p = a0p + 24 * RQU;
        const ull* c0p = (const ull*)Cs + (size_t)tj * RQU + hq;
        const ull* c1p = c0p + 16 * RQU;
        const ull* wp  = (const ull*)(w2s + ho) + hq;

        #pragma unroll 8
        for (int q = 0; q < 32; q++) {
            ull a0 = a0p[q];
            ull a1 = a1p[q];
            ull a2 = a2p[q];
            ull a3 = a3p[q];
            ull c0 = c0p[q];
            ull c1 = c1p[q];
            ull w  = wp[q];
            acc00 = fma2(relu2(add2(a0, c0)), w, acc00);
            acc01 = fma2(relu2(add2(a0, c1)), w, acc01);
            acc10 = fma2(relu2(add2(a1, c0)), w, acc10);
            acc11 = fma2(relu2(add2(a1, c1)), w, acc11);
            acc20 = fma2(relu2(add2(a2, c0)), w, acc20);
            acc21 = fma2(relu2(add2(a2, c1)), w, acc21);
            acc30 = fma2(relu2(add2(a3, c0)), w, acc30);
            acc31 = fma2(relu2(add2(a3, c1)), w, acc31);
        }
    }

    // ---- reduce hh halves ----
    float v0 = hsum2(acc00), v1 = hsum2(acc01);
    float v2 = hsum2(acc10), v3 = hsum2(acc11);
    float v4 = hsum2(acc20), v5 = hsum2(acc21);
    float v6 = hsum2(acc30), v7 = hsum2(acc31);

    int p = tid & 127;
    if (hh == 1) {
        psum[p][0] = v0; psum[p][1] = v1; psum[p][2] = v2; psum[p][3] = v3;
        psum[p][4] = v4; psum[p][5] = v5; psum[p][6] = v6; psum[p][7] = v7;
    }
    __syncthreads();
    if (hh == 0) {
        float b2v = b2[0];
        v0 += psum[p][0]; v1 += psum[p][1]; v2 += psum[p][2]; v3 += psum[p][3];
        v4 += psum[p][4]; v5 += psum[p][5]; v6 += psum[p][6]; v7 += psum[p][7];
        size_t base = ((size_t)(b * N)) * N;
        size_t r0 = base + (size_t)(i0 + ti) * N + j0;
        out[r0 + tj]               = v0 + b2v;
        out[r0 + tj + 16]          = v1 + b2v;
        out[r0 + 8 * N + tj]       = v2 + b2v;
        out[r0 + 8 * N + tj + 16]  = v3 + b2v;
        out[r0 + 16 * N + tj]      = v4 + b2v;
        out[r0 + 16 * N + tj + 16] = v5 + b2v;
        out[r0 + 24 * N + tj]      = v6 + b2v;
        out[r0 + 24 * N + tj + 16] = v7 + b2v;
    }
}

// ---------------------------------------------------------------------------
extern "C" void kernel_launch(void* const* d_in, const int* in_sizes, int n_in,
                              void* d_out, int out_size) {
    const float* x   = (const float*)d_in[0];  // [B,N,F]
    const float* Wp  = (const float*)d_in[1];  // [F,F]
    const float* W1  = (const float*)d_in[2];  // [3F,H]
    const float* b1  = (const float*)d_in[3];  // [H]
    const float* W2  = (const float*)d_in[4];  // [H,1]
    const float* b2  = (const float*)d_in[5];  // [1]
    float* out = (float*)d_out;                // [B,N,N,1]

    k_main<<<260, 256>>>(x, Wp, W1, b1);
    k_pair<<<dim3(N / 32, N / 32, B), 256>>>(W2, b2, out);
}